// round 13
// baseline (speedup 1.0000x reference)
#include <cuda_runtime.h>

// ChamferDistance: B=4, N=M=8192, 3-D Gaussian points.
// Output (float32): [dist1 | dist2 | idx1 | idx2], each B*N.
//
// Bit-exact pruned NN search, warp-autonomous (zero barriers in main kernel).
//  sort_kernel: per (cloud,b) block: smem hist -> scan -> scatter -> pair-pack
//    (refs stored negated+pair-interleaved; ids carried alongside).
//  chamfer_main: one warp owns 32 consecutive sorted queries. Stage A scans a
//    warp-uniform entry band around the warp's ref-rank range (broadcast LDG)
//    -> per-query upper bound bd. Warp window [min(x-s), max(x+s)] via shfl,
//    s = sqrt(bd)*1.0001+1e-3 (guard >> all fp rounding; d >= rn(dx^2) chain).
//    bin_of is monotone with exact edges, so rank range [P[bin(wlo)],
//    P[bin(whi)+1]) is a provable superset of every ref with d <= bd,
//    including exact ties. Dense scan of that range minus the stage-A band.
//  Distances: packed f32x2 (rn, no FMA), per-lane identical to the reference
//    ((dx^2+dy^2)+dz^2). Winner = min u64 key (d_bits<<32)|ref_id:
//    order-independent, ties -> lowest original ref id == jnp.argmin. Hence
//    scatter nondeterminism / window over-coverage cannot change the output.

#define BATCH 4
#define NPTS  8192
#define NBINS 128
#define NENT  (NPTS / 2)
#define TPB   128
#define KINF  0xFFFFFFFFFFFFFFFFull

typedef unsigned long long u64;
typedef unsigned int u32;

__device__ float4 g_sorted[2][BATCH][NPTS];        // {x,y,z,bitcast(id)}
__device__ ulonglong2 g_pairs[2][BATCH][NENT][2];  // pair-packed negated refs
__device__ int g_prefix[2][BATCH][NBINS + 1];

__device__ __forceinline__ u64 f2_add(u64 a, u64 b) {
    u64 r; asm("add.rn.f32x2 %0, %1, %2;" : "=l"(r) : "l"(a), "l"(b)); return r;
}
__device__ __forceinline__ u64 f2_mul(u64 a, u64 b) {
    u64 r; asm("mul.rn.f32x2 %0, %1, %2;" : "=l"(r) : "l"(a), "l"(b)); return r;
}
__device__ __forceinline__ u64 f2_pack(float lo, float hi) {
    u64 r; asm("mov.b64 %0, {%1, %2};" : "=l"(r) : "f"(lo), "f"(hi)); return r;
}
__device__ __forceinline__ void f2_unpack(float& lo, float& hi, u64 v) {
    asm("mov.b64 {%0, %1}, %2;" : "=f"(lo), "=f"(hi) : "l"(v));
}
__device__ __forceinline__ int bin_of(float x) {   // weakly monotone, exact edges
    int v = (int)floorf((x + 8.0f) * 8.0f);
    return min(max(v, 0), NBINS - 1);
}
__device__ __forceinline__ void eval_entry(u64 qx2, u64 qy2, u64 qz2,
                                           ulonglong2 v0, ulonglong2 v1,
                                           u64& bkey) {
    u64 dx = f2_add(qx2, v0.x);
    u64 dy = f2_add(qy2, v0.y);
    u64 dz = f2_add(qz2, v1.x);
    u64 d2 = f2_add(f2_add(f2_mul(dx, dx), f2_mul(dy, dy)), f2_mul(dz, dz));
    float dlo, dhi;
    f2_unpack(dlo, dhi, d2);
    u64 ka = ((u64)__float_as_uint(dlo) << 32) | (u32)(v1.y);
    u64 kb = ((u64)__float_as_uint(dhi) << 32) | (u32)(v1.y >> 32);
    if (ka < bkey) bkey = ka;
    if (kb < bkey) bkey = kb;
}

// ---- fused counting sort + pair pack: one block per (cloud, b) ----------

__global__ void __launch_bounds__(512)
sort_kernel(const float* __restrict__ xyz1, const float* __restrict__ xyz2) {
    const int c = blockIdx.x >> 2, b = blockIdx.x & 3;
    const float* src = (c ? xyz2 : xyz1) + (size_t)b * NPTS * 3;
    const int t = threadIdx.x;
    __shared__ int sh[NBINS], scur[NBINS];

    for (int i = t; i < NBINS; i += 512) sh[i] = 0;
    __syncthreads();
    for (int i = t; i < NPTS; i += 512)
        atomicAdd(&sh[bin_of(src[i * 3])], 1);
    __syncthreads();
    if (t == 0) {
        int run = 0;
        for (int i = 0; i < NBINS; i++) {
            scur[i] = run;
            g_prefix[c][b][i] = run;
            run += sh[i];
        }
        g_prefix[c][b][NBINS] = run;   // == NPTS
    }
    __syncthreads();
    for (int i = t; i < NPTS; i += 512) {
        const float x = src[i * 3], y = src[i * 3 + 1], z = src[i * 3 + 2];
        const int pos = atomicAdd(&scur[bin_of(x)], 1);
        g_sorted[c][b][pos] = make_float4(x, y, z, __int_as_float(i));
    }
    __syncthreads();
    for (int e = t; e < NENT; e += 512) {
        const float4 s0 = g_sorted[c][b][2 * e];
        const float4 s1 = g_sorted[c][b][2 * e + 1];
        g_pairs[c][b][e][0] = make_ulonglong2(f2_pack(-s0.x, -s1.x),
                                              f2_pack(-s0.y, -s1.y));
        const u64 idp = ((u64)(u32)__float_as_int(s1.w) << 32) |
                        (u32)__float_as_int(s0.w);
        g_pairs[c][b][e][1] = make_ulonglong2(f2_pack(-s0.z, -s1.z), idp);
    }
}

// ---- main: warp-autonomous stage-A + rank-exact window scan -------------

__global__ void __launch_bounds__(TPB)
chamfer_main(float* __restrict__ out) {
    const int db   = blockIdx.x >> 6;               // 0..7
    const int dir  = db >> 2, b = db & 3;
    const int qc   = dir, rc = 1 - qc;
    const int wr   = (blockIdx.x & 63) * (TPB / 32) + (threadIdx.x >> 5);
    const int lane = threadIdx.x & 31;
    const int qi   = wr * 32 + lane;                // sorted query index

    const float4 qp = g_sorted[qc][b][qi];
    const u64 qx2 = f2_pack(qp.x, qp.x);
    const u64 qy2 = f2_pack(qp.y, qp.y);
    const u64 qz2 = f2_pack(qp.z, qp.z);
    const int* __restrict__ P = g_prefix[rc][b];
    const ulonglong2* __restrict__ pr = &g_pairs[rc][b][0][0];

    // Warp x-range of the 32 queries (shfl reduction; sort is bin-granular
    // so reduce actual coords, don't trust endpoints).
    float xmin = qp.x, xmax = qp.x;
#pragma unroll
    for (int o = 16; o; o >>= 1) {
        xmin = fminf(xmin, __shfl_xor_sync(0xFFFFFFFFu, xmin, o));
        xmax = fmaxf(xmax, __shfl_xor_sync(0xFFFFFFFFu, xmax, o));
    }

    u64 bkey = KINF;

    // Warp-uniform range scan via broadcast LDG, unrolled 4 for MLP.
#define SCAN_RANGE(LO, HI)                                                   \
    {                                                                        \
        int base = (LO);                                                     \
        const int hi_ = (HI);                                                \
        for (; base + 4 <= hi_; base += 4) {                                 \
            ulonglong2 w0[4], w1[4];                                         \
            _Pragma("unroll")                                                \
            for (int u = 0; u < 4; u++) {                                    \
                w0[u] = pr[2 * (base + u)];                                  \
                w1[u] = pr[2 * (base + u) + 1];                              \
            }                                                                \
            _Pragma("unroll")                                                \
            for (int u = 0; u < 4; u++)                                      \
                eval_entry(qx2, qy2, qz2, w0[u], w1[u], bkey);               \
        }                                                                    \
        for (; base < hi_; base++)                                           \
            eval_entry(qx2, qy2, qz2, pr[2 * base], pr[2 * base + 1], bkey); \
    }

    // Stage A: band around the warp's ref-rank range -> finite bounds.
    const int e0 = max((P[bin_of(xmin)] >> 1) - 48, 0);
    const int e1 = min(((P[bin_of(xmax) + 1] + 1) >> 1) + 48, NENT);
    SCAN_RANGE(e0, e1)

    // Per-query window, warp union.
    {
        const float bd = __uint_as_float((u32)(bkey >> 32));
        const float s = sqrtf(bd) * 1.0001f + 1e-3f;  // guard >> fp rounding
        float wlo = qp.x - s, whi = qp.x + s;
#pragma unroll
        for (int o = 16; o; o >>= 1) {
            wlo = fminf(wlo, __shfl_xor_sync(0xFFFFFFFFu, wlo, o));
            whi = fmaxf(whi, __shfl_xor_sync(0xFFFFFFFFu, whi, o));
        }
        const int elo = P[bin_of(wlo)] >> 1;
        const int ehi = (P[bin_of(whi) + 1] + 1) >> 1;

        // Scan window minus the already-scanned stage-A band (idempotent).
        const int a  = min(max(e0, elo), ehi);
        const int b2 = min(max(e1, elo), ehi);
        SCAN_RANGE(elo, a)
        SCAN_RANGE(b2, ehi)
    }
#undef SCAN_RANGE

    const int qid    = __float_as_int(qp.w);
    const int ref_id = (int)(u32)(bkey & 0xFFFFFFFFu);
    const int n = BATCH * NPTS;
    out[dir * n + b * NPTS + qid]       = __uint_as_float((u32)(bkey >> 32));
    out[(2 + dir) * n + b * NPTS + qid] = (float)ref_id;
}

extern "C" void kernel_launch(void* const* d_in, const int* in_sizes, int n_in,
                              void* d_out, int out_size) {
    const float* xyz1 = (const float*)d_in[0];
    const float* xyz2 = (const float*)d_in[1];
    float* out = (float*)d_out;

    sort_kernel<<<8, 512>>>(xyz1, xyz2);
    chamfer_main<<<512, TPB>>>(out);   // 8 db-groups x 64 blocks x 4 warps
}

// round 14
// speedup vs baseline: 1.7261x; 1.7261x over previous
#include <cuda_runtime.h>

// ChamferDistance: B=4, N=M=8192, 3-D Gaussian points.
// Output (float32): [dist1 | dist2 | idx1 | idx2], each B*N.
//
// Bit-exact pruned NN search; R11 smem engine + fine bins + small tiles.
//  sort_kernel: per (cloud,b) block: smem hist -> scan -> scatter -> pair-pack
//    (512 bins over [-4,4], width 1/64 exact; edge bins catch outliers).
//  chamfer_main: 64-query tiles, 1 query/thread. Stage A scans the tile's
//    rank band (+-32 entries) via smem chunks -> per-query upper bound bd.
//    Tile window [min(x-s), max(x+s)], s = sqrt(bd)*1.0001+1e-3 (guard >>
//    all fp rounding; d >= rn(dx^2) chain; bin edges exact; bin_of monotone)
//    -> rank range [P[bin(wlo)], P[bin(whi)+1]) is a provable superset of
//    every ref with d <= bd including exact ties. Dense chunked smem scan.
//  Distances: packed f32x2 (rn, no FMA; the x2 lanes are the two refs of a
//    pair entry), per-lane identical to reference ((dx^2+dy^2)+dz^2).
//  Winner = min u64 key (d_bits<<32)|ref_id: order-independent, ties ->
//  lowest original ref id == jnp.argmin first-index. Scatter-order
//  nondeterminism / window over-coverage / band overlap cannot change output.

#define BATCH 4
#define NPTS  8192
#define NBINS 512
#define NENT  (NPTS / 2)
#define QTILE 64
#define TPB   64
#define CHUNK 64               // pair entries per smem stage (2 KB)
#define KINF  0xFFFFFFFFFFFFFFFFull

typedef unsigned long long u64;
typedef unsigned int u32;

__device__ float4 g_sorted[2][BATCH][NPTS];        // {x,y,z,bitcast(id)}
__device__ ulonglong2 g_pairs[2][BATCH][NENT][2];  // pair-packed negated refs
__device__ int g_prefix[2][BATCH][NBINS + 1];

__device__ __forceinline__ u64 f2_add(u64 a, u64 b) {
    u64 r; asm("add.rn.f32x2 %0, %1, %2;" : "=l"(r) : "l"(a), "l"(b)); return r;
}
__device__ __forceinline__ u64 f2_mul(u64 a, u64 b) {
    u64 r; asm("mul.rn.f32x2 %0, %1, %2;" : "=l"(r) : "l"(a), "l"(b)); return r;
}
__device__ __forceinline__ u64 f2_pack(float lo, float hi) {
    u64 r; asm("mov.b64 %0, {%1, %2};" : "=l"(r) : "f"(lo), "f"(hi)); return r;
}
__device__ __forceinline__ void f2_unpack(float& lo, float& hi, u64 v) {
    asm("mov.b64 {%0, %1}, %2;" : "=f"(lo), "=f"(hi) : "l"(v));
}
__device__ __forceinline__ int bin_of(float x) {   // weakly monotone, exact edges k/64
    int v = (int)floorf((x + 4.0f) * 64.0f);
    return min(max(v, 0), NBINS - 1);
}
__device__ __forceinline__ void eval_entry(u64 qx2, u64 qy2, u64 qz2,
                                           ulonglong2 v0, ulonglong2 v1,
                                           u64& bkey) {
    u64 dx = f2_add(qx2, v0.x);
    u64 dy = f2_add(qy2, v0.y);
    u64 dz = f2_add(qz2, v1.x);
    u64 d2 = f2_add(f2_add(f2_mul(dx, dx), f2_mul(dy, dy)), f2_mul(dz, dz));
    float dlo, dhi;
    f2_unpack(dlo, dhi, d2);
    u64 ka = ((u64)__float_as_uint(dlo) << 32) | (u32)(v1.y);
    u64 kb = ((u64)__float_as_uint(dhi) << 32) | (u32)(v1.y >> 32);
    if (ka < bkey) bkey = ka;
    if (kb < bkey) bkey = kb;
}

// ---- fused counting sort + pair pack: one block per (cloud, b) ----------

__global__ void __launch_bounds__(512)
sort_kernel(const float* __restrict__ xyz1, const float* __restrict__ xyz2) {
    const int c = blockIdx.x >> 2, b = blockIdx.x & 3;
    const float* src = (c ? xyz2 : xyz1) + (size_t)b * NPTS * 3;
    const int t = threadIdx.x;
    __shared__ int sh[NBINS], scur[NBINS];

    for (int i = t; i < NBINS; i += 512) sh[i] = 0;
    __syncthreads();
    for (int i = t; i < NPTS; i += 512)
        atomicAdd(&sh[bin_of(src[i * 3])], 1);
    __syncthreads();
    if (t == 0) {
        int run = 0;
        for (int i = 0; i < NBINS; i++) {
            scur[i] = run;
            g_prefix[c][b][i] = run;
            run += sh[i];
        }
        g_prefix[c][b][NBINS] = run;   // == NPTS
    }
    __syncthreads();
    for (int i = t; i < NPTS; i += 512) {
        const float x = src[i * 3], y = src[i * 3 + 1], z = src[i * 3 + 2];
        const int pos = atomicAdd(&scur[bin_of(x)], 1);
        g_sorted[c][b][pos] = make_float4(x, y, z, __int_as_float(i));
    }
    __syncthreads();
    for (int e = t; e < NENT; e += 512) {
        const float4 s0 = g_sorted[c][b][2 * e];
        const float4 s1 = g_sorted[c][b][2 * e + 1];
        g_pairs[c][b][e][0] = make_ulonglong2(f2_pack(-s0.x, -s1.x),
                                              f2_pack(-s0.y, -s1.y));
        const u64 idp = ((u64)(u32)__float_as_int(s1.w) << 32) |
                        (u32)__float_as_int(s0.w);
        g_pairs[c][b][e][1] = make_ulonglong2(f2_pack(-s0.z, -s1.z), idp);
    }
}

// ---- main: stage-A bound + rank-exact window scan, smem-staged ----------

__global__ void __launch_bounds__(TPB)
chamfer_main(float* __restrict__ out) {
    __shared__ __align__(16) ulonglong2 sbuf[CHUNK][2];
    __shared__ float rlo[TPB], rhi[TPB];

    const int tile = blockIdx.x, db = blockIdx.y;
    const int dir = db >> 2, b = db & 3;
    const int qc = dir, rc = 1 - qc;
    const int t = threadIdx.x;

    const float4 qp = g_sorted[qc][b][tile * QTILE + t];
    const u64 qx2 = f2_pack(qp.x, qp.x);
    const u64 qy2 = f2_pack(qp.y, qp.y);
    const u64 qz2 = f2_pack(qp.z, qp.z);
    const int* __restrict__ P = g_prefix[rc][b];
    const ulonglong2* __restrict__ pr = &g_pairs[rc][b][0][0];

    u64 bkey = KINF;

#define SCAN_RANGE(LO, HI)                                                  \
    for (int base = (LO); base < (HI); base += CHUNK) {                     \
        const int m = min(CHUNK, (HI) - base);                              \
        __syncthreads();                                                    \
        if (t < m) {                                                        \
            sbuf[t][0] = pr[2 * (base + t)];                                \
            sbuf[t][1] = pr[2 * (base + t) + 1];                            \
        }                                                                   \
        __syncthreads();                                                    \
        _Pragma("unroll 4")                                                 \
        for (int e = 0; e < m; e++)                                         \
            eval_entry(qx2, qy2, qz2, sbuf[e][0], sbuf[e][1], bkey);        \
    }

    // Tile x-range (sort is bin-granular; reduce actual coords).
    rlo[t] = qp.x; rhi[t] = qp.x;
    __syncthreads();
    for (int o = TPB / 2; o > 0; o >>= 1) {
        if (t < o) {
            rlo[t] = fminf(rlo[t], rlo[t + o]);
            rhi[t] = fmaxf(rhi[t], rhi[t + o]);
        }
        __syncthreads();
    }
    const float xmin = rlo[0], xmax = rhi[0];
    __syncthreads();

    // Stage A: band around the tile's ref-rank range -> finite bounds.
    const int e0 = max((P[bin_of(xmin)] >> 1) - 32, 0);
    const int e1 = min(((P[bin_of(xmax) + 1] + 1) >> 1) + 32, NENT);
    SCAN_RANGE(e0, e1)

    // Per-query window, tile union (fine bins make the lookup nearly exact).
    {
        const float bd = __uint_as_float((u32)(bkey >> 32));
        const float s = sqrtf(bd) * 1.0001f + 1e-3f;  // guard >> fp rounding
        __syncthreads();
        rlo[t] = qp.x - s; rhi[t] = qp.x + s;
        __syncthreads();
        for (int o = TPB / 2; o > 0; o >>= 1) {
            if (t < o) {
                rlo[t] = fminf(rlo[t], rlo[t + o]);
                rhi[t] = fmaxf(rhi[t], rhi[t + o]);
            }
            __syncthreads();
        }
    }
    const int elo = P[bin_of(rlo[0])] >> 1;
    const int ehi = (P[bin_of(rhi[0]) + 1] + 1) >> 1;

    // Scan window minus the already-scanned stage-A band (idempotent).
    const int a  = min(max(e0, elo), ehi);
    const int b2 = min(max(e1, elo), ehi);
    SCAN_RANGE(elo, a)
    SCAN_RANGE(b2, ehi)
#undef SCAN_RANGE

    const int qid    = __float_as_int(qp.w);
    const int ref_id = (int)(u32)(bkey & 0xFFFFFFFFu);
    const int n = BATCH * NPTS;
    out[dir * n + b * NPTS + qid]       = __uint_as_float((u32)(bkey >> 32));
    out[(2 + dir) * n + b * NPTS + qid] = (float)ref_id;
}

extern "C" void kernel_launch(void* const* d_in, const int* in_sizes, int n_in,
                              void* d_out, int out_size) {
    const float* xyz1 = (const float*)d_in[0];
    const float* xyz2 = (const float*)d_in[1];
    float* out = (float*)d_out;

    sort_kernel<<<8, 512>>>(xyz1, xyz2);
    chamfer_main<<<dim3(NPTS / QTILE, 8), TPB>>>(out);  // 1024 blocks
}

// round 16
// speedup vs baseline: 2.0111x; 1.1651x over previous
#include <cuda_runtime.h>

// ChamferDistance: B=4, N=M=8192, 3-D Gaussian points.
// Output (float32): [dist1 | dist2 | idx1 | idx2], each B*N.
//
// Bit-exact pruned NN search with a 2-D (x,y) cell grid.
//  sort_kernel: per (cloud,b): counting sort by cell = (xbin*64 + ybin),
//    64x64 cells of width 0.125 (exact edges, clamped) -> cell-major order:
//    within an x-bin, refs are y-bin sorted and contiguous in rank.
//  chamfer_main: block = (x-bin, 64-query chunk, dir*b); queries of one x-bin
//    are y-local. Stage A: +-48 entries around the first query's own-cell
//    rank (y-near seeds -> tight bound). Window: per-query [x+-s],[y+-s]
//    with s = sqrt(bd)*1.0001+1e-3 (guard >= all fp rounding; d >= rn(dx^2),
//    rn(dy^2)); block union -> for each x-bin in window, ONE contiguous rank
//    range [P[xb*64+bylo], P[xb*64+byhi+1]) -- a provable superset of every
//    ref with d <= bd, including exact ties (bin maps are weakly monotone
//    with exact edges; clamping is consistent for both clouds).
//  Distances: packed f32x2 (rn, no FMA; lanes = the 2 refs of a pair entry),
//    per-lane identical to reference ((dx^2+dy^2)+dz^2). Winner = min u64 key
//    (d_bits<<32)|ref_id: order-independent, ties -> lowest original ref id
//    == jnp.argmin. Scatter nondeterminism / over-coverage cannot change it.

#define BATCH 4
#define NPTS  8192
#define NXB   64
#define NYB   64
#define NCELLS (NXB * NYB)
#define NENT  (NPTS / 2)
#define TPB   64
#define CHUNK 64
#define KCH   9                 // query chunks per x-bin (64*9=576 > max bin count)
#define KINF  0xFFFFFFFFFFFFFFFFull

typedef unsigned long long u64;
typedef unsigned int u32;

__device__ float4 g_sorted[2][BATCH][NPTS];        // {x,y,z,bitcast(id)}
__device__ ulonglong2 g_pairs[2][BATCH][NENT][2];  // pair-packed negated refs
__device__ int g_prefix[2][BATCH][NCELLS + 1];

__device__ __forceinline__ u64 f2_add(u64 a, u64 b) {
    u64 r; asm("add.rn.f32x2 %0, %1, %2;" : "=l"(r) : "l"(a), "l"(b)); return r;
}
__device__ __forceinline__ u64 f2_mul(u64 a, u64 b) {
    u64 r; asm("mul.rn.f32x2 %0, %1, %2;" : "=l"(r) : "l"(a), "l"(b)); return r;
}
__device__ __forceinline__ u64 f2_pack(float lo, float hi) {
    u64 r; asm("mov.b64 %0, {%1, %2};" : "=l"(r) : "f"(lo), "f"(hi)); return r;
}
__device__ __forceinline__ void f2_unpack(float& lo, float& hi, u64 v) {
    asm("mov.b64 {%0, %1}, %2;" : "=f"(lo), "=f"(hi) : "l"(v));
}
__device__ __forceinline__ int xbin(float x) {   // weakly monotone, exact edges k/8
    int v = (int)floorf((x + 4.0f) * 8.0f);
    return min(max(v, 0), NXB - 1);
}
__device__ __forceinline__ int ybin(float y) {
    int v = (int)floorf((y + 4.0f) * 8.0f);
    return min(max(v, 0), NYB - 1);
}
__device__ __forceinline__ void eval_entry(u64 qx2, u64 qy2, u64 qz2,
                                           ulonglong2 v0, ulonglong2 v1,
                                           u64& bkey) {
    u64 dx = f2_add(qx2, v0.x);
    u64 dy = f2_add(qy2, v0.y);
    u64 dz = f2_add(qz2, v1.x);
    u64 d2 = f2_add(f2_add(f2_mul(dx, dx), f2_mul(dy, dy)), f2_mul(dz, dz));
    float dlo, dhi;
    f2_unpack(dlo, dhi, d2);
    u64 ka = ((u64)__float_as_uint(dlo) << 32) | (u32)(v1.y);
    u64 kb = ((u64)__float_as_uint(dhi) << 32) | (u32)(v1.y >> 32);
    if (ka < bkey) bkey = ka;
    if (kb < bkey) bkey = kb;
}

// ---- fused counting sort by cell + pair pack: one block per (cloud,b) ---

__global__ void __launch_bounds__(512)
sort_kernel(const float* __restrict__ xyz1, const float* __restrict__ xyz2) {
    const int c = blockIdx.x >> 2, b = blockIdx.x & 3;
    const float* src = (c ? xyz2 : xyz1) + (size_t)b * NPTS * 3;
    const int t = threadIdx.x;
    __shared__ int sh[NCELLS], scur[NCELLS];
    __shared__ int tsum[512], tbase[512];

    for (int i = t; i < NCELLS; i += 512) sh[i] = 0;
    __syncthreads();
    for (int i = t; i < NPTS; i += 512) {
        const float x = src[i * 3], y = src[i * 3 + 1];
        atomicAdd(&sh[xbin(x) * NYB + ybin(y)], 1);
    }
    __syncthreads();
    {   // parallel exclusive scan of 4096 cells: 8 cells/thread + warp scan
        int s = 0;
#pragma unroll
        for (int j = 0; j < 8; j++) s += sh[t * 8 + j];
        tsum[t] = s;
    }
    __syncthreads();
    if (t < 32) {
        int lsum = 0;
        for (int j = 0; j < 16; j++) lsum += tsum[t * 16 + j];
        // Inclusive warp scan (all lanes participate in every shfl).
        for (int o = 1; o < 32; o <<= 1) {
            const int v = __shfl_up_sync(0xFFFFFFFFu, lsum, o);
            if (t >= o) lsum += v;
        }
        // Exclusive value: previous lane's inclusive sum (shfl executed by
        // ALL lanes uniformly; selection happens after).
        const int prev = __shfl_up_sync(0xFFFFFFFFu, lsum, 1);
        int run = (t == 0) ? 0 : prev;
        for (int j = 0; j < 16; j++) {
            tbase[t * 16 + j] = run;
            run += tsum[t * 16 + j];
        }
    }
    __syncthreads();
    {
        int run = tbase[t];
#pragma unroll
        for (int j = 0; j < 8; j++) {
            const int cell = t * 8 + j;
            scur[cell] = run;
            g_prefix[c][b][cell] = run;
            run += sh[cell];
        }
    }
    if (t == 0) g_prefix[c][b][NCELLS] = NPTS;
    __syncthreads();
    for (int i = t; i < NPTS; i += 512) {
        const float x = src[i * 3], y = src[i * 3 + 1], z = src[i * 3 + 2];
        const int pos = atomicAdd(&scur[xbin(x) * NYB + ybin(y)], 1);
        g_sorted[c][b][pos] = make_float4(x, y, z, __int_as_float(i));
    }
    __syncthreads();
    for (int e = t; e < NENT; e += 512) {
        const float4 s0 = g_sorted[c][b][2 * e];
        const float4 s1 = g_sorted[c][b][2 * e + 1];
        g_pairs[c][b][e][0] = make_ulonglong2(f2_pack(-s0.x, -s1.x),
                                              f2_pack(-s0.y, -s1.y));
        const u64 idp = ((u64)(u32)__float_as_int(s1.w) << 32) |
                        (u32)__float_as_int(s0.w);
        g_pairs[c][b][e][1] = make_ulonglong2(f2_pack(-s0.z, -s1.z), idp);
    }
}

// ---- main: bin-aligned tiles, 2-D rank-exact windows --------------------

__global__ void __launch_bounds__(TPB)
chamfer_main(float* __restrict__ out) {
    __shared__ __align__(16) ulonglong2 sbuf[CHUNK][2];
    __shared__ float rlo[TPB], rhi[TPB];
    __shared__ int scell;

    const int bx = blockIdx.x, k = blockIdx.y, db = blockIdx.z;
    const int dir = db >> 2, b = db & 3;
    const int qc = dir, rc = 1 - qc;
    const int t = threadIdx.x;

    const int* __restrict__ Pq = g_prefix[qc][b];
    const int* __restrict__ Pr = g_prefix[rc][b];
    const int Qlo = Pq[bx * NYB], Qhi = Pq[(bx + 1) * NYB];
    const int qstart = Qlo + k * TPB;
    if (qstart >= Qhi) return;          // empty chunk: whole block exits

    const bool valid = (qstart + t) < Qhi;
    const int qi = valid ? (qstart + t) : qstart;   // clamp to a real query
    const float4 qp = g_sorted[qc][b][qi];
    const u64 qx2 = f2_pack(qp.x, qp.x);
    const u64 qy2 = f2_pack(qp.y, qp.y);
    const u64 qz2 = f2_pack(qp.z, qp.z);
    const ulonglong2* __restrict__ pr = &g_pairs[rc][b][0][0];

    u64 bkey = KINF;

#define SCAN_RANGE(LO, HI)                                                  \
    for (int base = (LO); base < (HI); base += CHUNK) {                     \
        const int m = min(CHUNK, (HI) - base);                              \
        __syncthreads();                                                    \
        if (t < m) {                                                        \
            sbuf[t][0] = pr[2 * (base + t)];                                \
            sbuf[t][1] = pr[2 * (base + t) + 1];                            \
        }                                                                   \
        __syncthreads();                                                    \
        _Pragma("unroll 4")                                                 \
        for (int e = 0; e < m; e++)                                         \
            eval_entry(qx2, qy2, qz2, sbuf[e][0], sbuf[e][1], bkey);        \
    }

    // Stage A: +-48 entries around the first query's own-cell rank (y-near
    // seeds -> tight upper bound). Any scanned set is a valid bound source.
    if (t == 0) scell = xbin(qp.x) * NYB + ybin(qp.y);
    __syncthreads();
    const int c0 = Pr[scell], c1 = Pr[scell + 1];
    const int e0 = max((c0 >> 1) - 48, 0);
    const int e1 = min(((c1 + 1) >> 1) + 48, NENT);
    SCAN_RANGE(e0, e1)

    // Per-query window, block union (x then y via the same smem arrays).
    const float bd = __uint_as_float((u32)(bkey >> 32));
    const float s = sqrtf(bd) * 1.0001f + 1e-3f;    // guard >> fp rounding
    float wxlo, wxhi, wylo, wyhi;
#pragma unroll
    for (int axis = 0; axis < 2; axis++) {
        const float v = axis ? qp.y : qp.x;
        __syncthreads();
        rlo[t] = valid ? v - s : 3.4e38f;
        rhi[t] = valid ? v + s : -3.4e38f;
        __syncthreads();
        for (int o = TPB / 2; o > 0; o >>= 1) {
            if (t < o) {
                rlo[t] = fminf(rlo[t], rlo[t + o]);
                rhi[t] = fmaxf(rhi[t], rhi[t + o]);
            }
            __syncthreads();
        }
        if (axis) { wylo = rlo[0]; wyhi = rhi[0]; }
        else      { wxlo = rlo[0]; wxhi = rhi[0]; }
    }

    const int bxlo = xbin(wxlo), bxhi = xbin(wxhi);
    const int bylo = ybin(wylo), byhi = ybin(wyhi);

    // One contiguous rank range per x-bin; subtract the stage-A band.
    for (int xb = bxlo; xb <= bxhi; xb++) {
        const int lo = Pr[xb * NYB + bylo] >> 1;
        const int hi = (Pr[xb * NYB + byhi + 1] + 1) >> 1;
        const int a  = min(max(e0, lo), hi);
        const int b2 = min(max(e1, lo), hi);
        SCAN_RANGE(lo, a)
        SCAN_RANGE(b2, hi)
    }
#undef SCAN_RANGE

    if (valid) {
        const int qid    = __float_as_int(qp.w);
        const int ref_id = (int)(u32)(bkey & 0xFFFFFFFFu);
        const int n = BATCH * NPTS;
        out[dir * n + b * NPTS + qid]       = __uint_as_float((u32)(bkey >> 32));
        out[(2 + dir) * n + b * NPTS + qid] = (float)ref_id;
    }
}

extern "C" void kernel_launch(void* const* d_in, const int* in_sizes, int n_in,
                              void* d_out, int out_size) {
    const float* xyz1 = (const float*)d_in[0];
    const float* xyz2 = (const float*)d_in[1];
    float* out = (float*)d_out;

    sort_kernel<<<8, 512>>>(xyz1, xyz2);
    chamfer_main<<<dim3(NXB, KCH, 8), TPB>>>(out);
}